// round 12
// baseline (speedup 1.0000x reference)
#include <cuda_runtime.h>
#include <math.h>

#define B 64
#define Cc 100
#define Ff 2048
#define T 32
#define H 300
#define NBLK 296   // 8 b-groups x 37 col-groups; exactly 2 blocks per SM
#define NGRP 8
#define CPG 37

// k_steps dynamic smem (floats): xs 2400 | sw 14400 | ex 288 | cs 72
#define XS_OFF   0
#define SW_OFF   2400
#define EX_OFF   16800
#define CS_OFF   17088
#define STEP_SMEM (17160 * 4)

typedef unsigned long long ull;

// packed f32x2 helpers (numerics identical to 2x fmaf)
__device__ __forceinline__ ull pk2(float x, float y) {
    ull r; asm("mov.b64 %0, {%1,%2};" : "=l"(r) : "f"(x), "f"(y)); return r;
}
__device__ __forceinline__ void fma2(ull& d, ull a, ull b) {
    asm("fma.rn.f32x2 %0, %1, %2, %3;" : "=l"(d) : "l"(a), "l"(b), "l"(d));
}
__device__ __forceinline__ float2 upk2(ull v) {
    float2 r; asm("mov.b64 {%0,%1}, %2;" : "=f"(r.x), "=f"(r.y) : "l"(v)); return r;
}

// ------------------- scratch (static device memory, no allocs) -------------------
__device__ float g_meanT[Ff * B];         // mean over C, transposed [f][b]
__device__ float g_eenc[B * Cc];          // enc @ We_enc
__device__ float g_attn[B * Cc];          // softmax(e_enc)  (time-invariant!)
__device__ float g_ctxT[Ff * B];          // ctx transposed [f][b]
__device__ float g_cT[H * B];             // cell state init [hh][b]
__device__ float g_hB[T * NGRP * H * 8];  // hidden state [t][bg][k][8]
__device__ float g_CWT[1504 * B];         // ctx @ gate ctx-rows (+Wcp), [j][b]
__device__ float g_baseT[31 * 1200 * B];  // per-step gate pre-act base [t][j][b]
__device__ float g_sbT[31 * H * B];       // sbase [t][k][b]
__device__ float g_pbT[31 * H * B];       // pbase = sbase@Wop + bop, [t][jj][b]
__device__ float g_WW[H * H];             // Whp @ Wop
__device__ float g_p0[8 * 600 * B];       // h0c0 k-split partials
__device__ float g_pcw[4 * 1500 * B];     // cw k-split partials
__device__ volatile unsigned g_arr[NBLK * 32];  // per-block arrival flags, 128B stride
__device__ volatile unsigned g_go2[NGRP * 32];  // per-b-group go words, 128B stride

// ------------------- prologue kernels -------------------

// one warp per (b,c) row: coalesced 512B/warp-load + shuffle reduce
__global__ void k_eenc(const float* __restrict__ enc, const float* __restrict__ We) {
    int w = blockIdx.x * 4 + (threadIdx.x >> 5);    // 1600 blocks x 128
    int lane = threadIdx.x & 31;
    if (w >= B * Cc) return;
    const float4* row = (const float4*)(enc + (size_t)w * Ff);
    const float4* wv = (const float4*)We;
    float s = 0.f;
#pragma unroll
    for (int i = 0; i < Ff / 4; i += 32) {
        float4 a = row[i + lane], c4 = wv[i + lane];
        s += a.x * c4.x + a.y * c4.y + a.z * c4.z + a.w * c4.w;
    }
#pragma unroll
    for (int o = 16; o > 0; o >>= 1) s += __shfl_down_sync(0xffffffffu, s, o);
    if (lane == 0) g_eenc[w] = s;
}

// softmax over C=100 per batch row. (h-dot and be are constant shifts -> dropped)
__global__ void k_softmax() {
    __shared__ float sv[128];
    int b = blockIdx.x, tid = threadIdx.x;
    float v = (tid < Cc) ? g_eenc[b * Cc + tid] : -1e30f;
    sv[tid] = v;
    __syncthreads();
    for (int s = 64; s > 0; s >>= 1) {
        if (tid < s) sv[tid] = fmaxf(sv[tid], sv[tid + s]);
        __syncthreads();
    }
    float mx = sv[0];
    __syncthreads();
    float e = (tid < Cc) ? expf(v - mx) : 0.f;
    sv[tid] = e;
    __syncthreads();
    for (int s = 64; s > 0; s >>= 1) {
        if (tid < s) sv[tid] += sv[tid + s];
        __syncthreads();
    }
    float inv = 1.0f / sv[0];
    if (tid < Cc) g_attn[b * Cc + tid] = e * inv;
}

// fused ctx+mean scan, float4 per thread: 256 blocks x 128 thr, 4 f per thread
__global__ void k_meanctx(const float* __restrict__ enc) {
    __shared__ float at[Cc];
    int b = blockIdx.x >> 2;
    int f4 = (blockIdx.x & 3) * 128 + threadIdx.x;  // 0..511
    if (threadIdx.x < Cc) at[threadIdx.x] = g_attn[b * Cc + threadIdx.x];
    __syncthreads();
    const float4* p = (const float4*)(enc + (size_t)b * Cc * Ff) + f4;
    float4 sc = make_float4(0.f, 0.f, 0.f, 0.f);
    float4 sm = make_float4(0.f, 0.f, 0.f, 0.f);
#pragma unroll 10
    for (int c = 0; c < Cc; c++) {
        float4 v = p[c * (Ff / 4)];
        float a = at[c];
        sc.x = fmaf(a, v.x, sc.x); sc.y = fmaf(a, v.y, sc.y);
        sc.z = fmaf(a, v.z, sc.z); sc.w = fmaf(a, v.w, sc.w);
        sm.x += v.x; sm.y += v.y; sm.z += v.z; sm.w += v.w;
    }
    int f = f4 * 4;
    g_ctxT[(f + 0) * B + b] = sc.x; g_ctxT[(f + 1) * B + b] = sc.y;
    g_ctxT[(f + 2) * B + b] = sc.z; g_ctxT[(f + 3) * B + b] = sc.w;
    const float r = 1.0f / Cc;
    g_meanT[(f + 0) * B + b] = sm.x * r; g_meanT[(f + 1) * B + b] = sm.y * r;
    g_meanT[(f + 2) * B + b] = sm.z * r; g_meanT[(f + 3) * B + b] = sm.w * r;
}

// h0/c0 partials: grid (30, 8). bx -> 20-col group (600 cols: 0..299 Wh0, 300..599 Wc0),
// by -> 256-k chunk (2 subs of 128). Thread: 4 cols.
__global__ void __launch_bounds__(320, 1) k_h0c0p(
        const float* __restrict__ Wh0, const float* __restrict__ Wc0) {
    __shared__ float4 xs4[128 * 16];    // 32 KB
    __shared__ float4 ws4[128 * 5];     // 10 KB  [kk][20 cols]
    int tid = threadIdx.x;
    int b = tid & 63, jq = tid >> 6;
    int colbase = blockIdx.x * 20;
    const float* W = (blockIdx.x >= 15) ? Wc0 : Wh0;
    int cb = (blockIdx.x >= 15) ? colbase - 300 : colbase;
    int kbase = blockIdx.y * 256;
    float* wsf = (float*)ws4;
    ull aA = pk2(0.f, 0.f), aB = pk2(0.f, 0.f);
    for (int sub = 0; sub < 2; sub++) {
        int k0 = kbase + sub * 128;
        __syncthreads();
        const float4* xsrc = (const float4*)g_meanT + k0 * 16;
        for (int i = tid; i < 2048; i += 320) xs4[i] = xsrc[i];
        for (int i = tid; i < 2560; i += 320) {
            int kk = i / 20, c = i - kk * 20;
            wsf[i] = W[(size_t)(k0 + kk) * H + cb + c];
        }
        __syncthreads();
        const float* xc = ((const float*)xs4) + b;
        const ulonglong2* wp = ((const ulonglong2*)ws4) + jq;
#pragma unroll 16
        for (int kk = 0; kk < 128; kk++) {
            float x = xc[kk * 64];
            ull xx = pk2(x, x);
            ulonglong2 w = wp[kk * 5];
            fma2(aA, xx, w.x);
            fma2(aB, xx, w.y);
        }
    }
    float2 rA = upk2(aA), rB = upk2(aB);
    float* dst = g_p0 + blockIdx.y * (600 * B) + (colbase + jq * 4) * B + b;
    dst[0] = rA.x; dst[B] = rA.y; dst[2 * B] = rB.x; dst[3 * B] = rB.y;
}

// CWT partials: grid (75, 4). bx -> 20-col group of j, by -> 512-k chunk (4 subs).
__global__ void __launch_bounds__(320, 1) k_cwp(
        const float* __restrict__ Wi, const float* __restrict__ Wf,
        const float* __restrict__ Wo, const float* __restrict__ Wg,
        const float* __restrict__ Wcp) {
    __shared__ float4 xs4[128 * 16];    // 32 KB
    __shared__ float4 ws4[128 * 5];     // 10 KB
    int tid = threadIdx.x;
    int b = tid & 63, jq = tid >> 6;
    int j0 = blockIdx.x * 20;
    const float* wbase;
    if (j0 < 1200) {
        int gate = j0 / 300, col = j0 - gate * 300;
        const float* Wx = (gate == 0) ? Wi : (gate == 1) ? Wf : (gate == 2) ? Wo : Wg;
        wbase = Wx + 600 * H + col;     // ctx rows start at comb row 600
    } else {
        wbase = Wcp + (j0 - 1200);
    }
    int kbase = blockIdx.y * 512;
    float* wsf = (float*)ws4;
    ull aA = pk2(0.f, 0.f), aB = pk2(0.f, 0.f);
    for (int sub = 0; sub < 4; sub++) {
        int k0 = kbase + sub * 128;
        __syncthreads();
        const float4* xsrc = (const float4*)g_ctxT + k0 * 16;
        for (int i = tid; i < 2048; i += 320) xs4[i] = xsrc[i];
        for (int i = tid; i < 2560; i += 320) {
            int kk = i / 20, c = i - kk * 20;
            wsf[i] = wbase[(size_t)(k0 + kk) * H + c];
        }
        __syncthreads();
        const float* xc = ((const float*)xs4) + b;
        const ulonglong2* wp = ((const ulonglong2*)ws4) + jq;
#pragma unroll 16
        for (int kk = 0; kk < 128; kk++) {
            float x = xc[kk * 64];
            ull xx = pk2(x, x);
            ulonglong2 w = wp[kk * 5];
            fma2(aA, xx, w.x);
            fma2(aB, xx, w.y);
        }
    }
    float2 rA = upk2(aA), rB = upk2(aB);
    float* dst = g_pcw + blockIdx.y * (1500 * B) + (j0 + jq * 4) * B + b;
    dst[0] = rA.x; dst[B] = rA.y; dst[2 * B] = rB.x; dst[3 * B] = rB.y;
}

// fused misc kernel: sb (from pcw directly) | cwred | h0red | ww | out0 | flag reset
__global__ void k_misc(const int* __restrict__ caps, const float* __restrict__ emb,
                       const float* __restrict__ bcp, const float* __restrict__ bhp,
                       const float* __restrict__ bh0, const float* __restrict__ bc0,
                       const float* __restrict__ Whp, const float* __restrict__ Wop,
                       float* __restrict__ out) {
    int idx = blockIdx.x * 256 + threadIdx.x;
    if (idx < 595200) {                          // sbT[t][k][b]
        int b = idx & 63, r = idx >> 6;
        int k = r % 300, t = r / 300;
        int cap = caps[b * T + t];
        float s = emb[(size_t)cap * H + k] + bcp[k] + bhp[k];
#pragma unroll
        for (int p = 0; p < 4; p++) s += g_pcw[p * 1500 * B + (1200 + k) * B + b];
        g_sbT[idx] = s;
    } else if (idx < 691200) {                   // cwred (96000)
        int i = idx - 595200;
        float s = 0.f;
#pragma unroll
        for (int p = 0; p < 4; p++) s += g_pcw[p * 1500 * B + i];
        g_CWT[i] = s;
    } else if (idx < 729600) {                   // h0red (38400)
        int i = idx - 691200;
        int col = i >> 6, b = i & 63;
        float s = 0.f;
#pragma unroll
        for (int j = 0; j < 8; j++) s += g_p0[j * 600 * B + i];
        if (col < 300) g_hB[(b >> 3) * (H * 8) + col * 8 + (b & 7)] = tanhf(s + bh0[col]);
        else           g_cT[(col - 300) * B + b] = tanhf(s + bc0[col - 300]);
    } else if (idx < 819600) {                   // ww (90000)
        int i = idx - 729600;
        int k = i / H, jj = i - k * H;
        float s = 0.f;
        const float* a = Whp + k * H;
        const float* w = Wop + jj;
#pragma unroll 4
        for (int m = 0; m < H; m++) s += a[m] * w[m * H];
        g_WW[i] = s;
    } else if (idx < 838800) {                   // out0 (19200)
        int i = idx - 819600;
        int b = i / H, jj = i - b * H;
        out[(size_t)b * T * H + jj] = emb[1 * H + jj];   // BOS = 1
    } else if (idx < 838800 + NBLK) {            // flag reset
        int f = idx - 838800;
        g_arr[f * 32] = 0;
        if (f < NGRP) g_go2[f * 32] = 0;
    }
}

// baseT[t][j][b] = bias_g[col] + CWT[j][b] + emb[cap[b][t]] @ (gate emb-rows)
__global__ void k_base(const int* __restrict__ caps, const float* __restrict__ emb,
                       const float* __restrict__ Wi, const float* __restrict__ Wf,
                       const float* __restrict__ Wo, const float* __restrict__ Wg,
                       const float* __restrict__ bi, const float* __restrict__ bf,
                       const float* __restrict__ bo, const float* __restrict__ bg) {
    __shared__ float xs[64 * 61];
    __shared__ float ws[300 * 20];      // 24 KB
    __shared__ int cap_s[64];
    int tid = threadIdx.x;              // 320
    int t = blockIdx.y;
    int b = tid & 63, jq = tid >> 6;
    int jB = blockIdx.x * 20;           // block col base; gate boundaries mult of 20
    int gate = jB / 300, colB = jB - gate * 300;
    int j0 = jB + jq * 4;
    int col0 = colB + jq * 4;
    const float* Wx = (gate == 0) ? Wi : (gate == 1) ? Wf : (gate == 2) ? Wo : Wg;
    const float* bx = (gate == 0) ? bi : (gate == 1) ? bf : (gate == 2) ? bo : bg;
    if (tid < 64) cap_s[tid] = caps[tid * T + t];
    for (int i = tid; i < 300 * 20; i += 320) {
        int kk = i / 20, c = i - kk * 20;
        ws[i] = Wx[(size_t)kk * H + colB + c];
    }
    __syncthreads();
    ull a01 = pk2(bx[col0 + 0] + g_CWT[(j0 + 0) * B + b],
                  bx[col0 + 1] + g_CWT[(j0 + 1) * B + b]);
    ull a23 = pk2(bx[col0 + 2] + g_CWT[(j0 + 2) * B + b],
                  bx[col0 + 3] + g_CWT[(j0 + 3) * B + b]);
    for (int c0 = 0; c0 < H; c0 += 60) {
        __syncthreads();
        for (int i = tid; i < 64 * 60; i += 320) {
            int bb = i / 60, kk = i - bb * 60;
            xs[bb * 61 + kk] = emb[(size_t)cap_s[bb] * H + c0 + kk];
        }
        __syncthreads();
        const float* wp = ws + c0 * 20 + jq * 4;
#pragma unroll 10
        for (int kk = 0; kk < 60; kk++) {
            float x = xs[b * 61 + kk];
            ull xx = pk2(x, x);
            ulonglong2 w = *(const ulonglong2*)(wp + kk * 20);
            fma2(a01, xx, w.x);
            fma2(a23, xx, w.y);
        }
    }
    float2 r01 = upk2(a01), r23 = upk2(a23);
    int base = t * 1200;
    g_baseT[(base + j0 + 0) * B + b] = r01.x;
    g_baseT[(base + j0 + 1) * B + b] = r01.y;
    g_baseT[(base + j0 + 2) * B + b] = r23.x;
    g_baseT[(base + j0 + 3) * B + b] = r23.y;
}

// pbT[t][jj][b] = bop[jj] + sum_k sbT[t][k][b] * Wop[k][jj]; w tile staged in smem
__global__ void k_pbase(const float* __restrict__ Wop, const float* __restrict__ bop) {
    __shared__ float ws[300 * 20];      // 24 KB
    int tid = threadIdx.x;              // 320
    int t = blockIdx.y;
    int b = tid & 63, jq = tid >> 6;
    int jB = blockIdx.x * 20;
    int j0 = jB + jq * 4;               // grid.x=15 -> j0 < 300
    for (int i = tid; i < 300 * 20; i += 320) {
        int kk = i / 20, c = i - kk * 20;
        ws[i] = Wop[(size_t)kk * H + jB + c];
    }
    __syncthreads();
    ull a01 = pk2(bop[j0], bop[j0 + 1]);
    ull a23 = pk2(bop[j0 + 2], bop[j0 + 3]);
    const float* xp = g_sbT + t * H * B + b;
    const float* wp = ws + jq * 4;
#pragma unroll 10
    for (int k = 0; k < H; k++) {
        float x = xp[k * B];
        ull xx = pk2(x, x);
        ulonglong2 w = *(const ulonglong2*)(wp + k * 20);
        fma2(a01, xx, w.x);
        fma2(a23, xx, w.y);
    }
    float2 r01 = upk2(a01), r23 = upk2(a23);
    int base = t * H;
    g_pbT[(base + j0 + 0) * B + b] = r01.x;
    g_pbT[(base + j0 + 1) * B + b] = r01.y;
    g_pbT[(base + j0 + 2) * B + b] = r23.x;
    g_pbT[(base + j0 + 3) * B + b] = r23.y;
}

// ------------------- persistent recurrence kernel (ONE launch, 32 steps) -------------------
// 296 blocks = 8 INDEPENDENT b-groups (8 b each) x 37 col-groups. EXACTLY 2 blocks per SM
// (guaranteed co-resident: 68.7KB smem, regs capped by launch_bounds) -> while one chain
// waits in its fence/poll/L2 latency, the co-resident chain computes. Barrier per 37 blocks.
__global__ void __launch_bounds__(320, 2) k_steps(
        const float* __restrict__ Wi, const float* __restrict__ Wf,
        const float* __restrict__ Wo, const float* __restrict__ Wg,
        float* __restrict__ out) {
    extern __shared__ float smem[];
    float* xs = smem + XS_OFF;          // [k][8]
    float* sw = smem + SW_OFF;          // [k][48] padded cols
    float* ex = smem + EX_OFF;          // [gate][ch*8+b], 4*72
    float* cs = smem + CS_OFF;          // [ch*8+b]

    int tid = threadIdx.x;
    int b = tid & 7, cq = tid >> 3;     // cq 0..39
    int bid = blockIdx.x;
    int bg = bid / CPG, cg = bid % CPG; // b-group, col-group
    int nh  = (cg < 4) ? 9 : 8;
    int hh0 = (cg < 4) ? cg * 9 : 36 + (cg - 4) * 8;
    int ncols = 5 * nh;                 // 40 or 45
    int bglob = bg * 8 + b;

    // ---- stage weight slice [k][48] (once); pad cols >= ncols with 0 ----
    for (int i = tid; i < 300 * 48; i += 320) {
        int k = i / 48, c = i - (i / 48) * 48;
        float v = 0.f;
        if (c < ncols) {
            int m = c / nh, ch = c - m * nh;
            if (m < 4) {
                const float* Wx = (m == 0) ? Wi : (m == 1) ? Wf : (m == 2) ? Wo : Wg;
                v = Wx[(size_t)(300 + k) * H + hh0 + ch];   // h rows of comb start at 300
            } else {
                v = g_WW[k * H + hh0 + ch];
            }
        }
        sw[i] = v;
    }
    if (tid < nh * 8) {
        cs[tid] = g_cT[(hh0 + (tid >> 3)) * B + bg * 8 + (tid & 7)];
    }
    // per-thread column info: col A = cq (always < ncols), col B = 40+cq (nh==9, cq<5)
    bool hasB = (40 + cq < ncols);
    int mA = cq / nh,        chA = cq - mA * nh;
    int mB = hasB ? ((40 + cq) / nh) : 0;
    int chB = hasB ? ((40 + cq) - mB * nh) : 0;
    int hhA = hh0 + chA, hhB = hh0 + chB;
    __syncthreads();

    for (int t = 0; t < T; t++) {
        // ---- stage h[t] for this b-group (9.6 KB) ----
        const float4* hsrc = (const float4*)(g_hB + ((size_t)t * NGRP + bg) * (H * 8));
        float4* xs4 = (float4*)xs;
        for (int j = tid; j < 600; j += 320) xs4[j] = hsrc[j];

        // ---- prefetch base/pb for this thread's cols (overlaps staging latency) ----
        float bvA = 0.f, bvB = 0.f;
        if (mA < 4) { if (t < 31) bvA = g_baseT[((t * 1200 + mA * 300 + hhA) << 6) + bglob]; }
        else        { if (t > 0)  bvA = g_pbT[(((t - 1) * 300 + hhA) << 6) + bglob]; }
        if (hasB) {
            if (mB < 4) { if (t < 31) bvB = g_baseT[((t * 1200 + mB * 300 + hhB) << 6) + bglob]; }
            else        { if (t > 0)  bvB = g_pbT[(((t - 1) * 300 + hhB) << 6) + bglob]; }
        }
        __syncthreads();

        // ---- dot: 1-2 full 300-k columns per thread ----
        float accA = bvA, accB = bvB;
        {
            const float* xk = xs + b;
            const float* wA = sw + cq;
            if (hasB) {
                const float* wB = sw + 40 + cq;
#pragma unroll 10
                for (int k = 0; k < 300; k++) {
                    float x = xk[k * 8];
                    accA = fmaf(x, wA[k * 48], accA);
                    accB = fmaf(x, wB[k * 48], accB);
                }
            } else {
#pragma unroll 10
                for (int k = 0; k < 300; k++) {
                    float x = xk[k * 8];
                    accA = fmaf(x, wA[k * 48], accA);
                }
            }
        }

        // ---- emit: pred straight to gmem; gates to smem exchange ----
        if (mA == 4) {
            if (t > 0) out[((size_t)bglob * T + t) * H + hhA] = accA;
        } else if (t < 31) {
            ex[mA * 72 + chA * 8 + b] = accA;
        }
        if (hasB) {
            if (mB == 4) {
                if (t > 0) out[((size_t)bglob * T + t) * H + hhB] = accB;
            } else if (t < 31) {
                ex[mB * 72 + chB * 8 + b] = accB;
            }
        }

        if (t < 31) {
            __syncthreads();
            // ---- pointwise LSTM update ----
            if (tid < nh * 8) {
                float ai = ex[tid];
                float af = ex[72 + tid];
                float ao = ex[144 + tid];
                float ag = ex[216 + tid];
                float iv = 1.f / (1.f + expf(-ai));
                float fv = 1.f / (1.f + expf(-af));
                float ov = 1.f / (1.f + expf(-ao));
                float gv = tanhf(ag);
                float cn = fv * cs[tid] + iv * gv;
                cs[tid] = cn;
                g_hB[((size_t)(t + 1) * NGRP + bg) * (H * 8) + (hh0 + (tid >> 3)) * 8 + (tid & 7)] = ov * tanhf(cn);
            }
            // ---- per-group two-level barrier (37 blocks) ----
            __threadfence();
            __syncthreads();
            unsigned tgt = (unsigned)(t + 1);
            if (cg == 0) {
                if (tid > 0 && tid < CPG) {
                    while (g_arr[(bg * CPG + tid) * 32] < tgt) { }
                }
                __syncthreads();
                if (tid == 0) { __threadfence(); g_go2[bg * 32] = tgt; }
            } else {
                if (tid == 0) {
                    g_arr[bid * 32] = tgt;
                    while (g_go2[bg * 32] < tgt) { }
                }
            }
            __syncthreads();
        }
    }
}

// ------------------- launch -------------------
extern "C" void kernel_launch(void* const* d_in, const int* in_sizes, int n_in,
                              void* d_out, int out_size) {
    const float* enc    = (const float*)d_in[0];
    const int*   caps   = (const int*)d_in[1];
    const float* emb    = (const float*)d_in[2];
    const float* Wh0    = (const float*)d_in[3];
    const float* bh0    = (const float*)d_in[4];
    const float* Wc0    = (const float*)d_in[5];
    const float* bc0    = (const float*)d_in[6];
    const float* We_enc = (const float*)d_in[7];
    // d_in[8] We_hid, d_in[9] be: unused — constant shifts inside softmax cancel.
    const float* Wi  = (const float*)d_in[10];
    const float* bi  = (const float*)d_in[11];
    const float* Wf  = (const float*)d_in[12];
    const float* bf  = (const float*)d_in[13];
    const float* Wo  = (const float*)d_in[14];
    const float* bo  = (const float*)d_in[15];
    const float* Wg  = (const float*)d_in[16];
    const float* bg  = (const float*)d_in[17];
    const float* Wcp = (const float*)d_in[18];
    const float* bcp = (const float*)d_in[19];
    const float* Whp = (const float*)d_in[20];
    const float* bhp = (const float*)d_in[21];
    const float* Wop = (const float*)d_in[22];
    const float* bop = (const float*)d_in[23];
    float* out = (float*)d_out;

    cudaFuncSetAttribute(k_steps, cudaFuncAttributeMaxDynamicSharedMemorySize, STEP_SMEM);

    k_eenc<<<1600, 128>>>(enc, We_enc);
    k_softmax<<<64, 128>>>();
    k_meanctx<<<256, 128>>>(enc);
    {
        dim3 gh(30, 8);
        k_h0c0p<<<gh, 320>>>(Wh0, Wc0);
    }
    {
        dim3 gc(75, 4);
        k_cwp<<<gc, 320>>>(Wi, Wf, Wo, Wg, Wcp);
    }
    k_misc<<<3279, 256>>>(caps, emb, bcp, bhp, bh0, bc0, Whp, Wop, out);
    {
        dim3 gb(60, 31);
        k_base<<<gb, 320>>>(caps, emb, Wi, Wf, Wo, Wg, bi, bf, bo, bg);
    }
    {
        dim3 gp(15, 31);
        k_pbase<<<gp, 320>>>(Wop, bop);
    }
    k_steps<<<NBLK, 320, STEP_SMEM>>>(Wi, Wf, Wo, Wg, out);
}

// round 13
// speedup vs baseline: 1.3031x; 1.3031x over previous
#include <cuda_runtime.h>
#include <math.h>

#define B 64
#define Cc 100
#define Ff 2048
#define T 32
#define H 300
#define NBLK 148   // persistent step-kernel grid == SM count

// k_steps dynamic smem: xs 19200 + sw 4800 + part 4800 + ex 768 + cs 192 = 29760 floats
#define XS_OFF   0
#define SW_OFF   19200
#define PART_OFF 24000
#define EX_OFF   28800
#define CS_OFF   29568
#define STEP_SMEM (29760 * 4)

typedef unsigned long long ull;

// packed f32x2 helpers (numerics identical to 2x fmaf)
__device__ __forceinline__ ull pk2(float x, float y) {
    ull r; asm("mov.b64 %0, {%1,%2};" : "=l"(r) : "f"(x), "f"(y)); return r;
}
__device__ __forceinline__ void fma2(ull& d, ull a, ull b) {
    asm("fma.rn.f32x2 %0, %1, %2, %3;" : "=l"(d) : "l"(a), "l"(b), "l"(d));
}
__device__ __forceinline__ float2 upk2(ull v) {
    float2 r; asm("mov.b64 {%0,%1}, %2;" : "=f"(r.x), "=f"(r.y) : "l"(v)); return r;
}
// scoped-ordering helpers: tid0-only release fence + acquire polls (NO per-thread
// __threadfence -> no 320x CCTL.IVALL L1-flush per step)
__device__ __forceinline__ void fence_rel_gpu() {
    asm volatile("fence.acq_rel.gpu;" ::: "memory");
}
__device__ __forceinline__ unsigned ld_acq(const volatile unsigned* p) {
    unsigned v;
    asm volatile("ld.acquire.gpu.u32 %0, [%1];" : "=r"(v) : "l"((const unsigned*)p) : "memory");
    return v;
}

// ------------------- scratch (static device memory, no allocs) -------------------
__device__ float g_meanT[Ff * B];         // mean over C, transposed [f][b]
__device__ float g_eenc[B * Cc];          // enc @ We_enc
__device__ float g_attn[B * Cc];          // softmax(e_enc)  (time-invariant!)
__device__ float g_ctxT[Ff * B];          // ctx transposed [f][b]
__device__ float g_cT[H * B];             // cell state init [hh][b]
__device__ float g_hB[T * H * B];         // hidden state [t][k][b], fresh rows per step
__device__ float g_CWT[1504 * B];         // ctx @ gate ctx-rows (+Wcp), [j][b]
__device__ float g_baseT[31 * 1200 * B];  // per-step gate pre-act base [t][j][b]
__device__ float g_sbT[31 * H * B];       // sbase [t][k][b]
__device__ float g_pbT[31 * H * B];       // pbase = sbase@Wop + bop, [t][jj][b]
__device__ float g_WW[H * H];             // Whp @ Wop
__device__ float g_p0[8 * 600 * B];       // h0c0 k-split partials
__device__ float g_pcw[4 * 1500 * B];     // cw k-split partials
__device__ volatile unsigned g_arr[NBLK * 32]; // per-block arrival flags, 128B stride
__device__ volatile unsigned g_go;             // broadcast go word

// ------------------- prologue kernels -------------------

// one warp per (b,c) row: coalesced 512B/warp-load + shuffle reduce
__global__ void k_eenc(const float* __restrict__ enc, const float* __restrict__ We) {
    int w = blockIdx.x * 4 + (threadIdx.x >> 5);    // 1600 blocks x 128
    int lane = threadIdx.x & 31;
    if (w >= B * Cc) return;
    const float4* row = (const float4*)(enc + (size_t)w * Ff);
    const float4* wv = (const float4*)We;
    float s = 0.f;
#pragma unroll
    for (int i = 0; i < Ff / 4; i += 32) {
        float4 a = row[i + lane], c4 = wv[i + lane];
        s += a.x * c4.x + a.y * c4.y + a.z * c4.z + a.w * c4.w;
    }
#pragma unroll
    for (int o = 16; o > 0; o >>= 1) s += __shfl_down_sync(0xffffffffu, s, o);
    if (lane == 0) g_eenc[w] = s;
}

// softmax over C=100 per batch row. (h-dot and be are constant shifts -> dropped)
__global__ void k_softmax() {
    __shared__ float sv[128];
    int b = blockIdx.x, tid = threadIdx.x;
    float v = (tid < Cc) ? g_eenc[b * Cc + tid] : -1e30f;
    sv[tid] = v;
    __syncthreads();
    for (int s = 64; s > 0; s >>= 1) {
        if (tid < s) sv[tid] = fmaxf(sv[tid], sv[tid + s]);
        __syncthreads();
    }
    float mx = sv[0];
    __syncthreads();
    float e = (tid < Cc) ? expf(v - mx) : 0.f;
    sv[tid] = e;
    __syncthreads();
    for (int s = 64; s > 0; s >>= 1) {
        if (tid < s) sv[tid] += sv[tid + s];
        __syncthreads();
    }
    float inv = 1.0f / sv[0];
    if (tid < Cc) g_attn[b * Cc + tid] = e * inv;
}

// fused ctx+mean scan, float4 per thread: 256 blocks x 128 thr, 4 f per thread
__global__ void k_meanctx(const float* __restrict__ enc) {
    __shared__ float at[Cc];
    int b = blockIdx.x >> 2;
    int f4 = (blockIdx.x & 3) * 128 + threadIdx.x;  // 0..511
    if (threadIdx.x < Cc) at[threadIdx.x] = g_attn[b * Cc + threadIdx.x];
    __syncthreads();
    const float4* p = (const float4*)(enc + (size_t)b * Cc * Ff) + f4;
    float4 sc = make_float4(0.f, 0.f, 0.f, 0.f);
    float4 sm = make_float4(0.f, 0.f, 0.f, 0.f);
#pragma unroll 10
    for (int c = 0; c < Cc; c++) {
        float4 v = p[c * (Ff / 4)];
        float a = at[c];
        sc.x = fmaf(a, v.x, sc.x); sc.y = fmaf(a, v.y, sc.y);
        sc.z = fmaf(a, v.z, sc.z); sc.w = fmaf(a, v.w, sc.w);
        sm.x += v.x; sm.y += v.y; sm.z += v.z; sm.w += v.w;
    }
    int f = f4 * 4;
    g_ctxT[(f + 0) * B + b] = sc.x; g_ctxT[(f + 1) * B + b] = sc.y;
    g_ctxT[(f + 2) * B + b] = sc.z; g_ctxT[(f + 3) * B + b] = sc.w;
    const float r = 1.0f / Cc;
    g_meanT[(f + 0) * B + b] = sm.x * r; g_meanT[(f + 1) * B + b] = sm.y * r;
    g_meanT[(f + 2) * B + b] = sm.z * r; g_meanT[(f + 3) * B + b] = sm.w * r;
}

// h0/c0 partials: grid (30, 8). bx -> 20-col group (600 cols: 0..299 Wh0, 300..599 Wc0),
// by -> 256-k chunk (2 subs of 128). Thread: 4 cols.
__global__ void __launch_bounds__(320, 1) k_h0c0p(
        const float* __restrict__ Wh0, const float* __restrict__ Wc0) {
    __shared__ float4 xs4[128 * 16];    // 32 KB
    __shared__ float4 ws4[128 * 5];     // 10 KB  [kk][20 cols]
    int tid = threadIdx.x;
    int b = tid & 63, jq = tid >> 6;
    int colbase = blockIdx.x * 20;
    const float* W = (blockIdx.x >= 15) ? Wc0 : Wh0;
    int cb = (blockIdx.x >= 15) ? colbase - 300 : colbase;
    int kbase = blockIdx.y * 256;
    float* wsf = (float*)ws4;
    ull aA = pk2(0.f, 0.f), aB = pk2(0.f, 0.f);
    for (int sub = 0; sub < 2; sub++) {
        int k0 = kbase + sub * 128;
        __syncthreads();
        const float4* xsrc = (const float4*)g_meanT + k0 * 16;
        for (int i = tid; i < 2048; i += 320) xs4[i] = xsrc[i];
        for (int i = tid; i < 2560; i += 320) {
            int kk = i / 20, c = i - kk * 20;
            wsf[i] = W[(size_t)(k0 + kk) * H + cb + c];
        }
        __syncthreads();
        const float* xc = ((const float*)xs4) + b;
        const ulonglong2* wp = ((const ulonglong2*)ws4) + jq;
#pragma unroll 16
        for (int kk = 0; kk < 128; kk++) {
            float x = xc[kk * 64];
            ull xx = pk2(x, x);
            ulonglong2 w = wp[kk * 5];
            fma2(aA, xx, w.x);
            fma2(aB, xx, w.y);
        }
    }
    float2 rA = upk2(aA), rB = upk2(aB);
    float* dst = g_p0 + blockIdx.y * (600 * B) + (colbase + jq * 4) * B + b;
    dst[0] = rA.x; dst[B] = rA.y; dst[2 * B] = rB.x; dst[3 * B] = rB.y;
}

// CWT partials: grid (75, 4). bx -> 20-col group of j, by -> 512-k chunk (4 subs).
__global__ void __launch_bounds__(320, 1) k_cwp(
        const float* __restrict__ Wi, const float* __restrict__ Wf,
        const float* __restrict__ Wo, const float* __restrict__ Wg,
        const float* __restrict__ Wcp) {
    __shared__ float4 xs4[128 * 16];    // 32 KB
    __shared__ float4 ws4[128 * 5];     // 10 KB
    int tid = threadIdx.x;
    int b = tid & 63, jq = tid >> 6;
    int j0 = blockIdx.x * 20;
    const float* wbase;
    if (j0 < 1200) {
        int gate = j0 / 300, col = j0 - gate * 300;
        const float* Wx = (gate == 0) ? Wi : (gate == 1) ? Wf : (gate == 2) ? Wo : Wg;
        wbase = Wx + 600 * H + col;     // ctx rows start at comb row 600
    } else {
        wbase = Wcp + (j0 - 1200);
    }
    int kbase = blockIdx.y * 512;
    float* wsf = (float*)ws4;
    ull aA = pk2(0.f, 0.f), aB = pk2(0.f, 0.f);
    for (int sub = 0; sub < 4; sub++) {
        int k0 = kbase + sub * 128;
        __syncthreads();
        const float4* xsrc = (const float4*)g_ctxT + k0 * 16;
        for (int i = tid; i < 2048; i += 320) xs4[i] = xsrc[i];
        for (int i = tid; i < 2560; i += 320) {
            int kk = i / 20, c = i - kk * 20;
            wsf[i] = wbase[(size_t)(k0 + kk) * H + c];
        }
        __syncthreads();
        const float* xc = ((const float*)xs4) + b;
        const ulonglong2* wp = ((const ulonglong2*)ws4) + jq;
#pragma unroll 16
        for (int kk = 0; kk < 128; kk++) {
            float x = xc[kk * 64];
            ull xx = pk2(x, x);
            ulonglong2 w = wp[kk * 5];
            fma2(aA, xx, w.x);
            fma2(aB, xx, w.y);
        }
    }
    float2 rA = upk2(aA), rB = upk2(aB);
    float* dst = g_pcw + blockIdx.y * (1500 * B) + (j0 + jq * 4) * B + b;
    dst[0] = rA.x; dst[B] = rA.y; dst[2 * B] = rB.x; dst[3 * B] = rB.y;
}

// fused misc kernel: sb (from pcw directly) | cwred | h0red | ww | out0 | flag reset
__global__ void k_misc(const int* __restrict__ caps, const float* __restrict__ emb,
                       const float* __restrict__ bcp, const float* __restrict__ bhp,
                       const float* __restrict__ bh0, const float* __restrict__ bc0,
                       const float* __restrict__ Whp, const float* __restrict__ Wop,
                       float* __restrict__ out) {
    int idx = blockIdx.x * 256 + threadIdx.x;
    if (idx < 595200) {                          // sbT[t][k][b]
        int b = idx & 63, r = idx >> 6;
        int k = r % 300, t = r / 300;
        int cap = caps[b * T + t];
        float s = emb[(size_t)cap * H + k] + bcp[k] + bhp[k];
#pragma unroll
        for (int p = 0; p < 4; p++) s += g_pcw[p * 1500 * B + (1200 + k) * B + b];
        g_sbT[idx] = s;
    } else if (idx < 691200) {                   // cwred (96000)
        int i = idx - 595200;
        float s = 0.f;
#pragma unroll
        for (int p = 0; p < 4; p++) s += g_pcw[p * 1500 * B + i];
        g_CWT[i] = s;
    } else if (idx < 729600) {                   // h0red (38400)
        int i = idx - 691200;
        int col = i >> 6, b = i & 63;
        float s = 0.f;
#pragma unroll
        for (int j = 0; j < 8; j++) s += g_p0[j * 600 * B + i];
        if (col < 300) g_hB[col * 64 + b] = tanhf(s + bh0[col]);
        else           g_cT[(col - 300) * B + b] = tanhf(s + bc0[col - 300]);
    } else if (idx < 819600) {                   // ww (90000)
        int i = idx - 729600;
        int k = i / H, jj = i - k * H;
        float s = 0.f;
        const float* a = Whp + k * H;
        const float* w = Wop + jj;
#pragma unroll 4
        for (int m = 0; m < H; m++) s += a[m] * w[m * H];
        g_WW[i] = s;
    } else if (idx < 838800) {                   // out0 (19200)
        int i = idx - 819600;
        int b = i / H, jj = i - b * H;
        out[(size_t)b * T * H + jj] = emb[1 * H + jj];   // BOS = 1
    } else if (idx < 838800 + NBLK) {            // flag reset
        int f = idx - 838800;
        g_arr[f * 32] = 0;
        if (f == 0) g_go = 0;
    }
}

// baseT[t][j][b] = bias_g[col] + CWT[j][b] + emb[cap[b][t]] @ (gate emb-rows)
__global__ void k_base(const int* __restrict__ caps, const float* __restrict__ emb,
                       const float* __restrict__ Wi, const float* __restrict__ Wf,
                       const float* __restrict__ Wo, const float* __restrict__ Wg,
                       const float* __restrict__ bi, const float* __restrict__ bf,
                       const float* __restrict__ bo, const float* __restrict__ bg) {
    __shared__ float xs[64 * 61];
    __shared__ float ws[300 * 20];      // 24 KB
    __shared__ int cap_s[64];
    int tid = threadIdx.x;              // 320
    int t = blockIdx.y;
    int b = tid & 63, jq = tid >> 6;
    int jB = blockIdx.x * 20;           // block col base; gate boundaries mult of 20
    int gate = jB / 300, colB = jB - gate * 300;
    int j0 = jB + jq * 4;
    int col0 = colB + jq * 4;
    const float* Wx = (gate == 0) ? Wi : (gate == 1) ? Wf : (gate == 2) ? Wo : Wg;
    const float* bx = (gate == 0) ? bi : (gate == 1) ? bf : (gate == 2) ? bo : bg;
    if (tid < 64) cap_s[tid] = caps[tid * T + t];
    for (int i = tid; i < 300 * 20; i += 320) {
        int kk = i / 20, c = i - kk * 20;
        ws[i] = Wx[(size_t)kk * H + colB + c];
    }
    __syncthreads();
    ull a01 = pk2(bx[col0 + 0] + g_CWT[(j0 + 0) * B + b],
                  bx[col0 + 1] + g_CWT[(j0 + 1) * B + b]);
    ull a23 = pk2(bx[col0 + 2] + g_CWT[(j0 + 2) * B + b],
                  bx[col0 + 3] + g_CWT[(j0 + 3) * B + b]);
    for (int c0 = 0; c0 < H; c0 += 60) {
        __syncthreads();
        for (int i = tid; i < 64 * 60; i += 320) {
            int bb = i / 60, kk = i - bb * 60;
            xs[bb * 61 + kk] = emb[(size_t)cap_s[bb] * H + c0 + kk];
        }
        __syncthreads();
        const float* wp = ws + c0 * 20 + jq * 4;
#pragma unroll 10
        for (int kk = 0; kk < 60; kk++) {
            float x = xs[b * 61 + kk];
            ull xx = pk2(x, x);
            ulonglong2 w = *(const ulonglong2*)(wp + kk * 20);
            fma2(a01, xx, w.x);
            fma2(a23, xx, w.y);
        }
    }
    float2 r01 = upk2(a01), r23 = upk2(a23);
    int base = t * 1200;
    g_baseT[(base + j0 + 0) * B + b] = r01.x;
    g_baseT[(base + j0 + 1) * B + b] = r01.y;
    g_baseT[(base + j0 + 2) * B + b] = r23.x;
    g_baseT[(base + j0 + 3) * B + b] = r23.y;
}

// pbT[t][jj][b] = bop[jj] + sum_k sbT[t][k][b] * Wop[k][jj]; w tile staged in smem
__global__ void k_pbase(const float* __restrict__ Wop, const float* __restrict__ bop) {
    __shared__ float ws[300 * 20];      // 24 KB
    int tid = threadIdx.x;              // 320
    int t = blockIdx.y;
    int b = tid & 63, jq = tid >> 6;
    int jB = blockIdx.x * 20;
    int j0 = jB + jq * 4;               // grid.x=15 -> j0 < 300
    for (int i = tid; i < 300 * 20; i += 320) {
        int kk = i / 20, c = i - kk * 20;
        ws[i] = Wop[(size_t)kk * H + jB + c];
    }
    __syncthreads();
    ull a01 = pk2(bop[j0], bop[j0 + 1]);
    ull a23 = pk2(bop[j0 + 2], bop[j0 + 3]);
    const float* xp = g_sbT + t * H * B + b;
    const float* wp = ws + jq * 4;
#pragma unroll 10
    for (int k = 0; k < H; k++) {
        float x = xp[k * B];
        ull xx = pk2(x, x);
        ulonglong2 w = *(const ulonglong2*)(wp + k * 20);
        fma2(a01, xx, w.x);
        fma2(a23, xx, w.y);
    }
    float2 r01 = upk2(a01), r23 = upk2(a23);
    int base = t * H;
    g_pbT[(base + j0 + 0) * B + b] = r01.x;
    g_pbT[(base + j0 + 1) * B + b] = r01.y;
    g_pbT[(base + j0 + 2) * B + b] = r23.x;
    g_pbT[(base + j0 + 3) * B + b] = r23.y;
}

// ------------------- persistent recurrence kernel (ONE launch, 32 steps) -------------------
// R10 structure (best measured): 148 blocks x 320 threads; blocks 0..3 own 3 hh cols,
// 4..147 own 2. h [k][b]: conflict-free scalar x-LDS + broadcast w-LDS. Warps split k
// (5 chunks x 2 b-groups); partials reduced via smem; base/pb prefetched; pred deferred.
// BARRIER CHANGE: tid0-only fence.acq_rel.gpu + acquire polls (no 320x CCTL.IVALL).
__global__ void __launch_bounds__(320, 1) k_steps(
        const float* __restrict__ Wi, const float* __restrict__ Wf,
        const float* __restrict__ Wo, const float* __restrict__ Wg,
        float* __restrict__ out) {
    extern __shared__ float smem[];
    float* xs   = smem + XS_OFF;        // [k][64]
    float* sw   = smem + SW_OFF;        // [k][16] cols mc = m*nc + c
    float* part = smem + PART_OFF;      // [mc][kw][64]
    float* ex   = smem + EX_OFF;        // [gate][c*64+b]
    float* cs   = smem + CS_OFF;        // [c*64+b]

    int tid = threadIdx.x;
    int w = tid >> 5, lane = tid & 31;
    int bg = w & 1, kw = w >> 1;
    int bb = bg * 32 + lane;            // this lane's b for the dot phase
    int k0 = kw * 60;
    int bid = blockIdx.x;
    int nc  = (bid < 4) ? 3 : 2;
    int hh0 = (bid < 4) ? bid * 3 : 12 + (bid - 4) * 2;
    int NMC = 5 * nc;

    // ---- stage weight slice [k][16] (once) ----
    for (int i = tid; i < 300 * 16; i += 320) {
        int k = i >> 4, mc = i & 15;
        float v = 0.f;
        if (mc < NMC) {
            int m, c;
            if (nc == 2) { m = mc >> 1; c = mc & 1; }
            else         { m = mc / 3;  c = mc - m * 3; }
            if (m < 4) {
                const float* Wx = (m == 0) ? Wi : (m == 1) ? Wf : (m == 2) ? Wo : Wg;
                v = Wx[(size_t)(300 + k) * H + hh0 + c];   // h rows of comb start at 300
            } else {
                v = g_WW[k * H + hh0 + c];
            }
        }
        sw[i] = v;
    }
    if (tid < nc * 64) {
        cs[tid] = g_cT[(hh0 + (tid >> 6)) * B + (tid & 63)];
    }
    // per-thread reduce-slot invariants (slot s -> output o = tid + s*320)
    int b2 = tid & 63;
    int ms[3], hhs[3], mcs[3];
#pragma unroll
    for (int s = 0; s < 3; s++) {
        int o = tid + s * 320;
        int mc = o >> 6;
        int m, c;
        if (nc == 2) { m = mc >> 1; c = mc & 1; }
        else         { m = mc / 3;  c = mc - m * 3; }
        ms[s] = m; hhs[s] = hh0 + c; mcs[s] = mc;
    }
    __syncthreads();

    for (int t = 0; t < T; t++) {
        // ---- stage h[t] ([k][b] global) into xs ----
        const float4* hsrc = (const float4*)(g_hB + (size_t)t * (H * B));
        float4* xs4 = (float4*)xs;
#pragma unroll
        for (int j = 0; j < 15; j++) xs4[tid + j * 320] = hsrc[tid + j * 320];

        // ---- prefetch base/pb for this thread's reduce slots (overlaps the dot) ----
        float bv[3];
#pragma unroll
        for (int s = 0; s < 3; s++) {
            bv[s] = 0.f;
            if (s < nc) {
                if (ms[s] < 4) {
                    if (t < 31) bv[s] = g_baseT[((t * 1200 + ms[s] * 300 + hhs[s]) << 6) + b2];
                } else {
                    if (t > 0)  bv[s] = g_pbT[(((t - 1) * 300 + hhs[s]) << 6) + b2];
                }
            }
        }
        __syncthreads();

        // ---- dot: this warp covers k in [k0,k0+60) for all NMC cols, its 32 b ----
        ull a0 = 0, a1 = 0, a2 = 0, a3 = 0, a4 = 0, a5 = 0, a6 = 0;
        float a14 = 0.f;
        const float* xk = xs + bb;
        if (nc == 2) {
#pragma unroll 10
            for (int kk = 0; kk < 60; kk++) {
                int k = k0 + kk;
                float x = xk[k * 64];
                ull xx = pk2(x, x);
                const float* swr = sw + k * 16;
                ulonglong2 wA = *(const ulonglong2*)(swr);
                ulonglong2 wB = *(const ulonglong2*)(swr + 4);
                ull wC = *(const ull*)(swr + 8);
                fma2(a0, xx, wA.x); fma2(a1, xx, wA.y);
                fma2(a2, xx, wB.x); fma2(a3, xx, wB.y);
                fma2(a4, xx, wC);
            }
        } else {
#pragma unroll 10
            for (int kk = 0; kk < 60; kk++) {
                int k = k0 + kk;
                float x = xk[k * 64];
                ull xx = pk2(x, x);
                const float* swr = sw + k * 16;
                ulonglong2 wA = *(const ulonglong2*)(swr);
                ulonglong2 wB = *(const ulonglong2*)(swr + 4);
                ulonglong2 wC = *(const ulonglong2*)(swr + 8);
                ull wD = *(const ull*)(swr + 12);
                fma2(a0, xx, wA.x); fma2(a1, xx, wA.y);
                fma2(a2, xx, wB.x); fma2(a3, xx, wB.y);
                fma2(a4, xx, wC.x); fma2(a5, xx, wC.y);
                fma2(a6, xx, wD);
                a14 = fmaf(x, swr[14], a14);
            }
        }
        // ---- write partials [mc][kw][b] ----
        {
            float* pb = part + kw * 64 + bb;
            float2 f;
            f = upk2(a0); pb[0 * 320] = f.x; pb[1 * 320] = f.y;
            f = upk2(a1); pb[2 * 320] = f.x; pb[3 * 320] = f.y;
            f = upk2(a2); pb[4 * 320] = f.x; pb[5 * 320] = f.y;
            f = upk2(a3); pb[6 * 320] = f.x; pb[7 * 320] = f.y;
            f = upk2(a4); pb[8 * 320] = f.x; pb[9 * 320] = f.y;
            if (nc == 3) {
                f = upk2(a5); pb[10 * 320] = f.x; pb[11 * 320] = f.y;
                f = upk2(a6); pb[12 * 320] = f.x; pb[13 * 320] = f.y;
                pb[14 * 320] = a14;
            }
        }
        __syncthreads();

        if (t < 31) {
            // ---- reduce GATE partials only (pred deferred past the barrier) ----
#pragma unroll
            for (int s = 0; s < 3; s++) {
                if (s < nc && ms[s] < 4) {
                    const float* pp = part + mcs[s] * 320 + b2;
                    float r = pp[0] + pp[64] + pp[128] + pp[192] + pp[256] + bv[s];
                    ex[ms[s] * 192 + (hhs[s] - hh0) * 64 + b2] = r;
                }
            }
            __syncthreads();
            // ---- pointwise LSTM update ----
            if (tid < nc * 64) {
                int c = tid >> 6, bbb = tid & 63;
                float ai = ex[tid];
                float af = ex[192 + tid];
                float ao = ex[384 + tid];
                float ag = ex[576 + tid];
                float iv = 1.f / (1.f + expf(-ai));
                float fv = 1.f / (1.f + expf(-af));
                float ov = 1.f / (1.f + expf(-ao));
                float gv = tanhf(ag);
                float cn = fv * cs[tid] + iv * gv;
                cs[tid] = cn;
                g_hB[(size_t)(t + 1) * (H * B) + (hh0 + c) * 64 + bbb] = ov * tanhf(cn);
            }
            // ---- two-level grid barrier: syncthreads (CTA-scope HB for h-writes) then
            //      tid0-only release fence + flag; acquire polls on the consumer side ----
            __syncthreads();
            unsigned tgt = (unsigned)(t + 1);
            if (bid == 0) {
                if (tid > 0 && tid < NBLK) {
                    while (ld_acq(&g_arr[tid * 32]) < tgt) { }
                }
                __syncthreads();
                if (tid == 0) { fence_rel_gpu(); g_go = tgt; }
            } else {
                if (tid == 0) {
                    fence_rel_gpu();
                    g_arr[bid * 32] = tgt;
                    while (ld_acq(&g_go) < tgt) { }
                }
            }
            __syncthreads();
        }

        // ---- deferred pred reduce + store (partials stay valid until next dot) ----
        if (t > 0) {
#pragma unroll
            for (int s = 0; s < 3; s++) {
                if (s < nc && ms[s] == 4) {
                    const float* pp = part + mcs[s] * 320 + b2;
                    float r = pp[0] + pp[64] + pp[128] + pp[192] + pp[256] + bv[s];
                    out[((size_t)b2 * T + t) * H + hhs[s]] = r;
                }
            }
        }
    }
}

// ------------------- launch -------------------
extern "C" void kernel_launch(void* const* d_in, const int* in_sizes, int n_in,
                              void* d_out, int out_size) {
    const float* enc    = (const float*)d_in[0];
    const int*   caps   = (const int*)d_in[1];
    const float* emb    = (const float*)d_in[2];
    const float* Wh0    = (const float*)d_in[3];
    const float* bh0    = (const float*)d_in[4];
    const float* Wc0    = (const float*)d_in[5];
    const float* bc0    = (const float*)d_in[6];
    const float* We_enc = (const float*)d_in[7];
    // d_in[8] We_hid, d_in[9] be: unused — constant shifts inside softmax cancel.
    const float* Wi  = (const float*)d_in[10];
    const float* bi  = (const float*)d_in[11];
    const float* Wf  = (const float*)d_in[12];
    const float* bf  = (const float*)d_in[13];
    const float* Wo  = (const float*)d_in[14];
    const float* bo  = (const float*)d_in[15];
    const float* Wg  = (const float*)d_in[16];
    const float* bg  = (const float*)d_in[17];
    const float* Wcp = (const float*)d_in[18];
    const float* bcp = (const float*)d_in[19];
    const float* Whp = (const float*)d_in[20];
    const float* bhp = (const float*)d_in[21];
    const float* Wop = (const float*)d_in[22];
    const float* bop = (const float*)d_in[23];
    float* out = (float*)d_out;

    cudaFuncSetAttribute(k_steps, cudaFuncAttributeMaxDynamicSharedMemorySize, STEP_SMEM);

    k_eenc<<<1600, 128>>>(enc, We_enc);
    k_softmax<<<64, 128>>>();
    k_meanctx<<<256, 128>>>(enc);
    {
        dim3 gh(30, 8);
        k_h0c0p<<<gh, 320>>>(Wh0, Wc0);
    }
    {
        dim3 gc(75, 4);
        k_cwp<<<gc, 320>>>(Wi, Wf, Wo, Wg, Wcp);
    }
    k_misc<<<3278, 256>>>(caps, emb, bcp, bhp, bh0, bc0, Whp, Wop, out);
    {
        dim3 gb(60, 31);
        k_base<<<gb, 320>>>(caps, emb, Wi, Wf, Wo, Wg, bi, bf, bo, bg);
    }
    {
        dim3 gp(15, 31);
        k_pbase<<<gp, 320>>>(Wop, bop);
    }
    k_steps<<<NBLK, 320, STEP_SMEM>>>(Wi, Wf, Wo, Wg, out);
}